// round 2
// baseline (speedup 1.0000x reference)
#include <cuda_runtime.h>
#include <cuda_bf16.h>

#define N_NODES 100000
#define N_EDGES 500000
#define FIN 128
#define D1 256
#define NHEADS 4
#define HID 64
#define OUTC 32
#define NEG_SLOPE 0.2f

// ---------------- scratch (device globals; no allocation) ----------------
__device__ float    g_xl1[N_NODES * D1];
__device__ float    g_xr1[N_NODES * D1];
__device__ float    g_acc1[N_NODES * D1];     // aggregation acc, then h (in-place relu)
__device__ float    g_alpha1[N_EDGES * NHEADS];
__device__ unsigned g_amax1[N_NODES * NHEADS];
__device__ float    g_den1[N_NODES * NHEADS];
__device__ float    g_xl2[N_NODES * OUTC];
__device__ float    g_xr2[N_NODES * OUTC];
__device__ float    g_acc2[N_NODES * OUTC];
__device__ float    g_alpha2[N_EDGES];
__device__ unsigned g_amax2[N_NODES];
__device__ float    g_den2[N_NODES];
__device__ int      g_src[N_EDGES];
__device__ int      g_dst[N_EDGES];

// ordered-uint encoding for float atomicMax
__device__ __forceinline__ unsigned fenc(float f) {
    unsigned u = __float_as_uint(f);
    return (u & 0x80000000u) ? ~u : (u | 0x80000000u);
}
__device__ __forceinline__ float fdec(unsigned u) {
    u = (u & 0x80000000u) ? (u & 0x7FFFFFFFu) : ~u;
    return __uint_as_float(u);
}

// ---------------- prep / init ----------------
// edge_index is int32 on device (JAX x64 disabled -> int64 request demotes to int32)
__global__ void k_prep(const int* __restrict__ ei) {
    int i = blockIdx.x * blockDim.x + threadIdx.x;
    if (i < N_EDGES) {
        g_src[i] = ei[i];
        g_dst[i] = ei[N_EDGES + i];
    }
}

__global__ void k_init1() {
    int i = blockIdx.x * blockDim.x + threadIdx.x;
    if (i < N_NODES * D1) g_acc1[i] = 0.f;
    if (i < N_NODES * NHEADS) { g_amax1[i] = 0u; g_den1[i] = 0.f; }
}

__global__ void k_init2() {
    int i = blockIdx.x * blockDim.x + threadIdx.x;
    if (i < N_NODES * OUTC) g_acc2[i] = 0.f;
    if (i < N_NODES) { g_amax2[i] = 0u; g_den2[i] = 0.f; }
}

// ---------------- tiled SGEMM with bias: C = A@B + bias ----------------
// BM=64, BN=64, BK=16, 256 threads, 4x4 microtile.
// MODE selects destination (device global) and, for layer 2, source A = g_acc1.
template<int MODE>
__global__ void sgemm_bias(const float* __restrict__ Aext,
                           const float* __restrict__ B,
                           const float* __restrict__ bias,
                           int M, int K, int Ncol) {
    const float* A = (MODE < 2) ? Aext : g_acc1;
    float* C = (MODE == 0) ? g_xl1 : (MODE == 1) ? g_xr1
             : (MODE == 2) ? g_xl2 : g_xr2;

    __shared__ float As[16][68];   // As[k][m]
    __shared__ float Bs[16][68];   // Bs[k][n]

    int tid = threadIdx.x;
    int tx = tid & 15, ty = tid >> 4;
    int row0 = blockIdx.y * 64;
    int col0 = blockIdx.x * 64;

    float acc[4][4];
#pragma unroll
    for (int i = 0; i < 4; i++)
#pragma unroll
        for (int j = 0; j < 4; j++) acc[i][j] = 0.f;

    int lr = tid >> 4;   // 0..15  (A row within 16-row chunk)
    int lc = tid & 15;   // 0..15  (A col)
    int br = tid >> 6;   // 0..3   (B row within 4-row chunk)
    int bc = tid & 63;   // 0..63  (B col)

    for (int kk = 0; kk < K; kk += 16) {
#pragma unroll
        for (int i = 0; i < 4; i++) {
            int r = row0 + lr + 16 * i;
            As[lc][lr + 16 * i] = (r < M) ? A[(long)r * K + kk + lc] : 0.f;
        }
#pragma unroll
        for (int i = 0; i < 4; i++) {
            int c = col0 + bc;
            Bs[br + 4 * i][bc] = (c < Ncol) ? B[(long)(kk + br + 4 * i) * Ncol + c] : 0.f;
        }
        __syncthreads();
#pragma unroll
        for (int k = 0; k < 16; k++) {
            float a[4], b[4];
#pragma unroll
            for (int i = 0; i < 4; i++) a[i] = As[k][ty * 4 + i];
#pragma unroll
            for (int j = 0; j < 4; j++) b[j] = Bs[k][tx * 4 + j];
#pragma unroll
            for (int i = 0; i < 4; i++)
#pragma unroll
                for (int j = 0; j < 4; j++) acc[i][j] += a[i] * b[j];
        }
        __syncthreads();
    }

#pragma unroll
    for (int i = 0; i < 4; i++) {
        int r = row0 + ty * 4 + i;
        if (r >= M) continue;
#pragma unroll
        for (int j = 0; j < 4; j++) {
            int c = col0 + tx * 4 + j;
            if (c < Ncol) C[(long)r * Ncol + c] = acc[i][j] + bias[c];
        }
    }
}

// ---------------- layer-1 edge kernels ----------------
// one warp per edge, lane covers channels [lane*8, lane*8+8), head = lane>>3
__global__ void k_edge_alpha1(const float* __restrict__ ea,
                              const float* __restrict__ We1,
                              const float* __restrict__ att1) {
    int gw = (blockIdx.x * blockDim.x + threadIdx.x) >> 5;
    if (gw >= N_EDGES) return;
    int lane = threadIdx.x & 31;
    int s = g_src[gw], d = g_dst[gw];
    float eav = ea[gw];
    int cb = lane * 8;

    const float4* L = (const float4*)(g_xl1 + (long)s * D1 + cb);
    const float4* R = (const float4*)(g_xr1 + (long)d * D1 + cb);
    const float4* W = (const float4*)(We1 + cb);
    const float4* T = (const float4*)(att1 + cb);   // att flat idx == channel idx

    float4 l0 = L[0], l1 = L[1];
    float4 r0 = R[0], r1 = R[1];
    float4 w0 = W[0], w1 = W[1];
    float4 a0 = T[0], a1 = T[1];

    float sum = 0.f;
#define TERM(LV, RV, WV, AV) { float v = (LV) + (RV) + eav * (WV); \
        v = (v > 0.f) ? v : NEG_SLOPE * v; sum += (AV) * v; }
    TERM(l0.x, r0.x, w0.x, a0.x); TERM(l0.y, r0.y, w0.y, a0.y);
    TERM(l0.z, r0.z, w0.z, a0.z); TERM(l0.w, r0.w, w0.w, a0.w);
    TERM(l1.x, r1.x, w1.x, a1.x); TERM(l1.y, r1.y, w1.y, a1.y);
    TERM(l1.z, r1.z, w1.z, a1.z); TERM(l1.w, r1.w, w1.w, a1.w);
#undef TERM

    sum += __shfl_down_sync(0xffffffffu, sum, 4, 8);
    sum += __shfl_down_sync(0xffffffffu, sum, 2, 8);
    sum += __shfl_down_sync(0xffffffffu, sum, 1, 8);

    if ((lane & 7) == 0) {
        int h = lane >> 3;
        g_alpha1[gw * NHEADS + h] = sum;
        atomicMax(&g_amax1[d * NHEADS + h], fenc(sum));
    }
}

__global__ void k_soft1() {
    int i = blockIdx.x * blockDim.x + threadIdx.x;
    if (i >= N_EDGES * NHEADS) return;
    int e = i >> 2, h = i & 3;
    int d = g_dst[e];
    float v = expf(g_alpha1[i] - fdec(g_amax1[d * NHEADS + h]));
    g_alpha1[i] = v;
    atomicAdd(&g_den1[d * NHEADS + h], v);
}

__global__ void k_agg1() {
    int gw = (blockIdx.x * blockDim.x + threadIdx.x) >> 5;
    if (gw >= N_EDGES) return;
    int lane = threadIdx.x & 31;
    int s = g_src[gw], d = g_dst[gw];
    int h = lane >> 3;
    float w = g_alpha1[gw * NHEADS + h] / (g_den1[d * NHEADS + h] + 1e-16f);
    int cb = lane * 8;
    const float4* L = (const float4*)(g_xl1 + (long)s * D1 + cb);
    float4 l0 = L[0], l1 = L[1];
    float* p = g_acc1 + (long)d * D1 + cb;
    atomicAdd(p + 0, l0.x * w); atomicAdd(p + 1, l0.y * w);
    atomicAdd(p + 2, l0.z * w); atomicAdd(p + 3, l0.w * w);
    atomicAdd(p + 4, l1.x * w); atomicAdd(p + 5, l1.y * w);
    atomicAdd(p + 6, l1.z * w); atomicAdd(p + 7, l1.w * w);
}

__global__ void k_relu1(const float* __restrict__ b1) {
    int i = blockIdx.x * blockDim.x + threadIdx.x;
    if (i >= N_NODES * D1) return;
    g_acc1[i] = fmaxf(g_acc1[i] + b1[i & (D1 - 1)], 0.f);
}

// ---------------- layer-2 edge kernels (heads=1, C=32) ----------------
__global__ void k_edge_alpha2(const float* __restrict__ ea,
                              const float* __restrict__ We2,
                              const float* __restrict__ att2) {
    int gw = (blockIdx.x * blockDim.x + threadIdx.x) >> 5;
    if (gw >= N_EDGES) return;
    int lane = threadIdx.x & 31;
    int s = g_src[gw], d = g_dst[gw];
    float eav = ea[gw];
    float v = g_xl2[s * OUTC + lane] + g_xr2[d * OUTC + lane] + eav * We2[lane];
    v = (v > 0.f) ? v : NEG_SLOPE * v;
    float p = att2[lane] * v;
#pragma unroll
    for (int o = 16; o > 0; o >>= 1) p += __shfl_down_sync(0xffffffffu, p, o);
    if (lane == 0) {
        g_alpha2[gw] = p;
        atomicMax(&g_amax2[d], fenc(p));
    }
}

__global__ void k_soft2() {
    int i = blockIdx.x * blockDim.x + threadIdx.x;
    if (i >= N_EDGES) return;
    int d = g_dst[i];
    float v = expf(g_alpha2[i] - fdec(g_amax2[d]));
    g_alpha2[i] = v;
    atomicAdd(&g_den2[d], v);
}

__global__ void k_agg2() {
    int gw = (blockIdx.x * blockDim.x + threadIdx.x) >> 5;
    if (gw >= N_EDGES) return;
    int lane = threadIdx.x & 31;
    int s = g_src[gw], d = g_dst[gw];
    float w = g_alpha2[gw] / (g_den2[d] + 1e-16f);
    atomicAdd(&g_acc2[d * OUTC + lane], g_xl2[s * OUTC + lane] * w);
}

__global__ void k_out(const float* __restrict__ b2, float* __restrict__ out) {
    int i = blockIdx.x * blockDim.x + threadIdx.x;
    if (i >= N_NODES * OUTC) return;
    out[i] = g_acc2[i] + b2[i & (OUTC - 1)];
}

// ---------------- launch ----------------
extern "C" void kernel_launch(void* const* d_in, const int* in_sizes, int n_in,
                              void* d_out, int out_size) {
    const float* x    = (const float*)d_in[0];
    const int*   ei   = (const int*)d_in[1];   // int32 (JAX demotes int64)
    const float* ea   = (const float*)d_in[2];
    const float* Wl1  = (const float*)d_in[3];
    const float* bl1  = (const float*)d_in[4];
    const float* Wr1  = (const float*)d_in[5];
    const float* br1  = (const float*)d_in[6];
    const float* We1  = (const float*)d_in[7];
    const float* att1 = (const float*)d_in[8];
    const float* b1   = (const float*)d_in[9];
    const float* Wl2  = (const float*)d_in[10];
    const float* bl2  = (const float*)d_in[11];
    const float* Wr2  = (const float*)d_in[12];
    const float* br2  = (const float*)d_in[13];
    const float* We2  = (const float*)d_in[14];
    const float* att2 = (const float*)d_in[15];
    const float* b2   = (const float*)d_in[16];
    float* out = (float*)d_out;

    k_prep<<<(N_EDGES + 255) / 256, 256>>>(ei);
    k_init1<<<(N_NODES * D1 + 255) / 256, 256>>>();

    dim3 g1((D1 + 63) / 64, (N_NODES + 63) / 64);
    sgemm_bias<0><<<g1, 256>>>(x, Wl1, bl1, N_NODES, FIN, D1);
    sgemm_bias<1><<<g1, 256>>>(x, Wr1, br1, N_NODES, FIN, D1);

    int ewarp_blocks = (N_EDGES * 32 + 255) / 256;
    k_edge_alpha1<<<ewarp_blocks, 256>>>(ea, We1, att1);
    k_soft1<<<(N_EDGES * NHEADS + 255) / 256, 256>>>();
    k_agg1<<<ewarp_blocks, 256>>>();
    k_relu1<<<(N_NODES * D1 + 255) / 256, 256>>>(b1);

    k_init2<<<(N_NODES * OUTC + 255) / 256, 256>>>();
    dim3 g2(1, (N_NODES + 63) / 64);
    sgemm_bias<2><<<g2, 256>>>(x, Wl2, bl2, N_NODES, D1, OUTC);
    sgemm_bias<3><<<g2, 256>>>(x, Wr2, br2, N_NODES, D1, OUTC);

    k_edge_alpha2<<<ewarp_blocks, 256>>>(ea, We2, att2);
    k_soft2<<<(N_EDGES + 255) / 256, 256>>>();
    k_agg2<<<ewarp_blocks, 256>>>();
    k_out<<<(N_NODES * OUTC + 255) / 256, 256>>>(b2, out);
}

// round 3
// speedup vs baseline: 1.3285x; 1.3285x over previous
#include <cuda_runtime.h>
#include <cuda_bf16.h>

#define N_NODES 100000
#define N_EDGES 500000
#define FIN 128
#define D1 256
#define NHEADS 4
#define HID 64
#define OUTC 32
#define NEG_SLOPE 0.2f

#define SCAN_B 512
#define SCAN_NB ((N_NODES + SCAN_B - 1) / SCAN_B)   // 196

// ---------------- scratch (device globals; no allocation) ----------------
__device__ float g_xl1[N_NODES * D1];
__device__ float g_xr1[N_NODES * D1];
__device__ float g_h1[N_NODES * D1];      // layer-1 output (post relu)
__device__ float g_xl2[N_NODES * OUTC];
__device__ float g_xr2[N_NODES * OUTC];
__device__ int   g_deg[N_NODES];
__device__ int   g_off[N_NODES + 1];      // exclusive offsets (also holds inclusive scan temporarily)
__device__ int   g_cursor[N_NODES];
__device__ int   g_bsum[SCAN_NB + 1];
__device__ int   g_ssrc[N_EDGES];         // src sorted by dst
__device__ float g_sea[N_EDGES];          // edge_attr sorted by dst

// ---------------- CSR build ----------------
__global__ void k_zero_deg() {
    int i = blockIdx.x * blockDim.x + threadIdx.x;
    if (i < N_NODES) g_deg[i] = 0;
}

// edge_index is int32 on device (JAX demotes int64 with x64 disabled)
__global__ void k_count(const int* __restrict__ ei) {
    int i = blockIdx.x * blockDim.x + threadIdx.x;
    if (i < N_EDGES) atomicAdd(&g_deg[ei[N_EDGES + i]], 1);
}

__global__ void k_scan1() {   // per-block inclusive scan of deg -> g_off, block totals -> g_bsum
    __shared__ int sh[SCAN_B];
    int t = threadIdx.x;
    int i = blockIdx.x * SCAN_B + t;
    int v = (i < N_NODES) ? g_deg[i] : 0;
    sh[t] = v;
    __syncthreads();
    for (int off = 1; off < SCAN_B; off <<= 1) {
        int add = (t >= off) ? sh[t - off] : 0;
        __syncthreads();
        sh[t] += add;
        __syncthreads();
    }
    if (i < N_NODES) g_off[i] = sh[t];
    if (t == SCAN_B - 1) g_bsum[blockIdx.x] = sh[t];
}

__global__ void k_scan2() {   // exclusive scan of block sums (single thread; 196 elems)
    if (threadIdx.x == 0) {
        int acc = 0;
        for (int b = 0; b < SCAN_NB; b++) {
            int v = g_bsum[b];
            g_bsum[b] = acc;
            acc += v;
        }
    }
}

__global__ void k_scan3() {   // finalize exclusive offsets + cursor
    int i = blockIdx.x * blockDim.x + threadIdx.x;
    if (i < N_NODES) {
        int excl = g_off[i] - g_deg[i] + g_bsum[i / SCAN_B];
        g_off[i] = excl;
        g_cursor[i] = excl;
    }
    if (i == 0) g_off[N_NODES] = N_EDGES;
}

__global__ void k_scatter(const int* __restrict__ ei, const float* __restrict__ ea) {
    int i = blockIdx.x * blockDim.x + threadIdx.x;
    if (i >= N_EDGES) return;
    int d = ei[N_EDGES + i];
    int pos = atomicAdd(&g_cursor[d], 1);
    g_ssrc[pos] = ei[i];
    g_sea[pos] = ea[i];
}

// ---------------- tiled SGEMM with bias: C = A@B + bias ----------------
template<int MODE>
__global__ void sgemm_bias(const float* __restrict__ Aext,
                           const float* __restrict__ B,
                           const float* __restrict__ bias,
                           int M, int K, int Ncol) {
    const float* A = (MODE < 2) ? Aext : g_h1;
    float* C = (MODE == 0) ? g_xl1 : (MODE == 1) ? g_xr1
             : (MODE == 2) ? g_xl2 : g_xr2;

    __shared__ float As[16][68];
    __shared__ float Bs[16][68];

    int tid = threadIdx.x;
    int tx = tid & 15, ty = tid >> 4;
    int row0 = blockIdx.y * 64;
    int col0 = blockIdx.x * 64;

    float acc[4][4];
#pragma unroll
    for (int i = 0; i < 4; i++)
#pragma unroll
        for (int j = 0; j < 4; j++) acc[i][j] = 0.f;

    int lr = tid >> 4;
    int lc = tid & 15;
    int br = tid >> 6;
    int bc = tid & 63;

    for (int kk = 0; kk < K; kk += 16) {
#pragma unroll
        for (int i = 0; i < 4; i++) {
            int r = row0 + lr + 16 * i;
            As[lc][lr + 16 * i] = (r < M) ? A[(long)r * K + kk + lc] : 0.f;
        }
#pragma unroll
        for (int i = 0; i < 4; i++) {
            int c = col0 + bc;
            Bs[br + 4 * i][bc] = (c < Ncol) ? B[(long)(kk + br + 4 * i) * Ncol + c] : 0.f;
        }
        __syncthreads();
#pragma unroll
        for (int k = 0; k < 16; k++) {
            float a[4], b[4];
#pragma unroll
            for (int i = 0; i < 4; i++) a[i] = As[k][ty * 4 + i];
#pragma unroll
            for (int j = 0; j < 4; j++) b[j] = Bs[k][tx * 4 + j];
#pragma unroll
            for (int i = 0; i < 4; i++)
#pragma unroll
                for (int j = 0; j < 4; j++) acc[i][j] += a[i] * b[j];
        }
        __syncthreads();
    }

#pragma unroll
    for (int i = 0; i < 4; i++) {
        int r = row0 + ty * 4 + i;
        if (r >= M) continue;
#pragma unroll
        for (int j = 0; j < 4; j++) {
            int c = col0 + tx * 4 + j;
            if (c < Ncol) C[(long)r * Ncol + c] = acc[i][j] + bias[c];
        }
    }
}

// ---------------- fused layer-1 node kernel ----------------
// warp per node; lane covers channels [lane*8, lane*8+8), head = lane>>3.
// online softmax over incident edges; writes h1 = relu(agg + b1).
__global__ void k_node1(const float* __restrict__ We1,
                        const float* __restrict__ att1,
                        const float* __restrict__ b1) {
    int node = (blockIdx.x * blockDim.x + threadIdx.x) >> 5;
    if (node >= N_NODES) return;
    int lane = threadIdx.x & 31;
    int cb = lane * 8;

    const float4* Rp = (const float4*)(g_xr1 + (long)node * D1 + cb);
    float4 r0 = Rp[0], r1 = Rp[1];
    const float4* Wp = (const float4*)(We1 + cb);
    float4 w0 = Wp[0], w1 = Wp[1];
    const float4* Tp = (const float4*)(att1 + cb);
    float4 a0 = Tp[0], a1 = Tp[1];

    float M = -3.0e38f, D = 0.f;
    float4 v0 = {0.f, 0.f, 0.f, 0.f}, v1 = {0.f, 0.f, 0.f, 0.f};

    int beg = g_off[node], end = g_off[node + 1];
    for (int k = beg; k < end; k++) {
        int s = g_ssrc[k];
        float eav = g_sea[k];
        const float4* Lp = (const float4*)(g_xl1 + (long)s * D1 + cb);
        float4 l0 = Lp[0], l1 = Lp[1];

        float p = 0.f;
#define TERM(LV, RV, WV, AV) { float t = (LV) + (RV) + eav * (WV); \
        t = (t > 0.f) ? t : NEG_SLOPE * t; p += (AV) * t; }
        TERM(l0.x, r0.x, w0.x, a0.x); TERM(l0.y, r0.y, w0.y, a0.y);
        TERM(l0.z, r0.z, w0.z, a0.z); TERM(l0.w, r0.w, w0.w, a0.w);
        TERM(l1.x, r1.x, w1.x, a1.x); TERM(l1.y, r1.y, w1.y, a1.y);
        TERM(l1.z, r1.z, w1.z, a1.z); TERM(l1.w, r1.w, w1.w, a1.w);
#undef TERM
        // reduce within 8-lane head group, broadcast to all 8 lanes
        p += __shfl_xor_sync(0xffffffffu, p, 4);
        p += __shfl_xor_sync(0xffffffffu, p, 2);
        p += __shfl_xor_sync(0xffffffffu, p, 1);

        float newM = fmaxf(M, p);
        float scale = expf(M - newM);
        float wgt = expf(p - newM);
        D = D * scale + wgt;
        v0.x = v0.x * scale + wgt * l0.x; v0.y = v0.y * scale + wgt * l0.y;
        v0.z = v0.z * scale + wgt * l0.z; v0.w = v0.w * scale + wgt * l0.w;
        v1.x = v1.x * scale + wgt * l1.x; v1.y = v1.y * scale + wgt * l1.y;
        v1.z = v1.z * scale + wgt * l1.z; v1.w = v1.w * scale + wgt * l1.w;
        M = newM;
    }

    float inv = 1.f / (D + 1e-16f);
    const float4* Bp = (const float4*)(b1 + cb);
    float4 bb0 = Bp[0], bb1 = Bp[1];
    float4 o0, o1;
    o0.x = fmaxf(v0.x * inv + bb0.x, 0.f); o0.y = fmaxf(v0.y * inv + bb0.y, 0.f);
    o0.z = fmaxf(v0.z * inv + bb0.z, 0.f); o0.w = fmaxf(v0.w * inv + bb0.w, 0.f);
    o1.x = fmaxf(v1.x * inv + bb1.x, 0.f); o1.y = fmaxf(v1.y * inv + bb1.y, 0.f);
    o1.z = fmaxf(v1.z * inv + bb1.z, 0.f); o1.w = fmaxf(v1.w * inv + bb1.w, 0.f);
    float4* Op = (float4*)(g_h1 + (long)node * D1 + cb);
    Op[0] = o0;
    Op[1] = o1;
}

// ---------------- fused layer-2 node kernel ----------------
// warp per node; lane = channel (32). Writes final output + b2.
__global__ void k_node2(const float* __restrict__ We2,
                        const float* __restrict__ att2,
                        const float* __restrict__ b2,
                        float* __restrict__ out) {
    int node = (blockIdx.x * blockDim.x + threadIdx.x) >> 5;
    if (node >= N_NODES) return;
    int lane = threadIdx.x & 31;

    float r = g_xr2[node * OUTC + lane];
    float w = We2[lane];
    float a = att2[lane];

    float M = -3.0e38f, D = 0.f, v = 0.f;

    int beg = g_off[node], end = g_off[node + 1];
    for (int k = beg; k < end; k++) {
        int s = g_ssrc[k];
        float eav = g_sea[k];
        float l = g_xl2[s * OUTC + lane];
        float t = l + r + eav * w;
        t = (t > 0.f) ? t : NEG_SLOPE * t;
        float p = a * t;
#pragma unroll
        for (int o = 16; o > 0; o >>= 1) p += __shfl_xor_sync(0xffffffffu, p, o);

        float newM = fmaxf(M, p);
        float scale = expf(M - newM);
        float wgt = expf(p - newM);
        D = D * scale + wgt;
        v = v * scale + wgt * l;
        M = newM;
    }

    out[node * OUTC + lane] = v / (D + 1e-16f) + b2[lane];
}

// ---------------- launch ----------------
extern "C" void kernel_launch(void* const* d_in, const int* in_sizes, int n_in,
                              void* d_out, int out_size) {
    const float* x    = (const float*)d_in[0];
    const int*   ei   = (const int*)d_in[1];
    const float* ea   = (const float*)d_in[2];
    const float* Wl1  = (const float*)d_in[3];
    const float* bl1  = (const float*)d_in[4];
    const float* Wr1  = (const float*)d_in[5];
    const float* br1  = (const float*)d_in[6];
    const float* We1  = (const float*)d_in[7];
    const float* att1 = (const float*)d_in[8];
    const float* b1   = (const float*)d_in[9];
    const float* Wl2  = (const float*)d_in[10];
    const float* bl2  = (const float*)d_in[11];
    const float* Wr2  = (const float*)d_in[12];
    const float* br2  = (const float*)d_in[13];
    const float* We2  = (const float*)d_in[14];
    const float* att2 = (const float*)d_in[15];
    const float* b2   = (const float*)d_in[16];
    float* out = (float*)d_out;

    // CSR build (counting sort by dst)
    k_zero_deg<<<(N_NODES + 255) / 256, 256>>>();
    k_count<<<(N_EDGES + 255) / 256, 256>>>(ei);
    k_scan1<<<SCAN_NB, SCAN_B>>>();
    k_scan2<<<1, 32>>>();
    k_scan3<<<(N_NODES + 255) / 256, 256>>>();
    k_scatter<<<(N_EDGES + 255) / 256, 256>>>(ei, ea);

    // layer-1 GEMMs
    dim3 g1((D1 + 63) / 64, (N_NODES + 63) / 64);
    sgemm_bias<0><<<g1, 256>>>(x, Wl1, bl1, N_NODES, FIN, D1);
    sgemm_bias<1><<<g1, 256>>>(x, Wr1, br1, N_NODES, FIN, D1);

    // fused layer-1 attention + aggregation + relu
    int nwb = (N_NODES * 32 + 255) / 256;
    k_node1<<<nwb, 256>>>(We1, att1, b1);

    // layer-2 GEMMs (A = g_h1)
    dim3 g2(1, (N_NODES + 63) / 64);
    sgemm_bias<2><<<g2, 256>>>(x, Wl2, bl2, N_NODES, D1, OUTC);
    sgemm_bias<3><<<g2, 256>>>(x, Wr2, br2, N_NODES, D1, OUTC);

    // fused layer-2 attention + aggregation + output
    k_node2<<<nwb, 256>>>(We2, att2, b2, out);
}

// round 5
// speedup vs baseline: 2.5927x; 1.9517x over previous
#include <cuda_runtime.h>
#include <cuda_bf16.h>

#define N_NODES 100000
#define N_EDGES 500000
#define FIN 128
#define D1 256
#define NHEADS 4
#define HID 64
#define OUTC 32
#define NEG_SLOPE 0.2f

#define SCAN_B 512
#define SCAN_NB ((N_NODES + SCAN_B - 1) / SCAN_B)   // 196

// ---------------- scratch (device globals; no allocation) ----------------
__device__ float g_xl1[N_NODES * D1];
__device__ float g_xr1[N_NODES * D1];
__device__ float g_h1[N_NODES * D1];
__device__ float g_xl2[N_NODES * OUTC];
__device__ float g_xr2[N_NODES * OUTC];
__device__ int   g_deg[N_NODES];
__device__ int   g_off[N_NODES + 1];
__device__ int   g_cursor[N_NODES];
__device__ int   g_bsum[SCAN_NB + 1];
__device__ int   g_ssrc[N_EDGES];
__device__ float g_sea[N_EDGES];

// ---------------- CSR build ----------------
__global__ void k_zero_deg() {
    int i = blockIdx.x * blockDim.x + threadIdx.x;
    if (i < N_NODES) g_deg[i] = 0;
}

__global__ void k_count(const int* __restrict__ ei) {
    int i = blockIdx.x * blockDim.x + threadIdx.x;
    if (i < N_EDGES) atomicAdd(&g_deg[ei[N_EDGES + i]], 1);
}

__global__ void k_scan1() {
    __shared__ int sh[SCAN_B];
    int t = threadIdx.x;
    int i = blockIdx.x * SCAN_B + t;
    int v = (i < N_NODES) ? g_deg[i] : 0;
    sh[t] = v;
    __syncthreads();
    for (int off = 1; off < SCAN_B; off <<= 1) {
        int add = (t >= off) ? sh[t - off] : 0;
        __syncthreads();
        sh[t] += add;
        __syncthreads();
    }
    if (i < N_NODES) g_off[i] = sh[t];
    if (t == SCAN_B - 1) g_bsum[blockIdx.x] = sh[t];
}

__global__ void k_scan2() {   // parallel exclusive scan of SCAN_NB block sums
    __shared__ int sh[256];
    int t = threadIdx.x;
    int v = (t < SCAN_NB) ? g_bsum[t] : 0;
    sh[t] = v;
    __syncthreads();
    for (int off = 1; off < 256; off <<= 1) {
        int add = (t >= off) ? sh[t - off] : 0;
        __syncthreads();
        sh[t] += add;
        __syncthreads();
    }
    if (t < SCAN_NB) g_bsum[t] = sh[t] - v;   // exclusive
}

__global__ void k_scan3() {
    int i = blockIdx.x * blockDim.x + threadIdx.x;
    if (i < N_NODES) {
        int excl = g_off[i] - g_deg[i] + g_bsum[i / SCAN_B];
        g_off[i] = excl;
        g_cursor[i] = excl;
    }
    if (i == 0) g_off[N_NODES] = N_EDGES;
}

__global__ void k_scatter(const int* __restrict__ ei, const float* __restrict__ ea) {
    int i = blockIdx.x * blockDim.x + threadIdx.x;
    if (i >= N_EDGES) return;
    int d = ei[N_EDGES + i];
    int pos = atomicAdd(&g_cursor[d], 1);
    g_ssrc[pos] = ei[i];
    g_sea[pos] = ea[i];
}

// ---------------- dual-output tiled SGEMM: [C0|C1] = A@[Bl|Br] + [bl|br] -------
// BM=128, BN=64, BK=16, 256 threads, 8x4 microtile.
// MODE 0: layer1 (A=x ext, K=128, SPLIT=256 -> g_xl1,g_xr1)
// MODE 1: layer2 (A=g_h1,  K=256, SPLIT=32  -> g_xl2,g_xr2)
template<int MODE>
__global__ void sgemm_dual(const float* __restrict__ Aext,
                           const float* __restrict__ Bl,
                           const float* __restrict__ Br,
                           const float* __restrict__ bl,
                           const float* __restrict__ br) {
    constexpr int K     = (MODE == 0) ? FIN : D1;
    constexpr int SPLIT = (MODE == 0) ? D1  : OUTC;
    const float* A  = (MODE == 0) ? Aext : g_h1;
    float*       C0 = (MODE == 0) ? g_xl1 : g_xl2;
    float*       C1 = (MODE == 0) ? g_xr1 : g_xr2;

    __shared__ float As[16][132];   // [k][m]
    __shared__ float Bs[16][68];    // [k][n]

    const int tid = threadIdx.x;
    const int tx = tid & 15;        // n group (0..15)
    const int ty = tid >> 4;        // m group (0..15)
    const int row0 = blockIdx.y * 128;
    const int col0 = blockIdx.x * 64;

    float acc[8][4];
#pragma unroll
    for (int i = 0; i < 8; i++)
#pragma unroll
        for (int j = 0; j < 4; j++) acc[i][j] = 0.f;

    for (int kk = 0; kk < K; kk += 16) {
        // load A tile: 128 rows x 16 k = 512 float4; 2 per thread
#pragma unroll
        for (int i = 0; i < 2; i++) {
            int f = tid * 2 + i;
            int arow = f >> 2;
            int kq = (f & 3) * 4;
            int r = row0 + arow;
            float4 v = {0.f, 0.f, 0.f, 0.f};
            if (r < N_NODES)
                v = *(const float4*)(A + (long)r * K + kk + kq);
            As[kq + 0][arow] = v.x;
            As[kq + 1][arow] = v.y;
            As[kq + 2][arow] = v.z;
            As[kq + 3][arow] = v.w;
        }
        // load B tile: 16 k x 64 n = 256 float4; 1 per thread
        {
            int krow = tid >> 4;
            int nq = (tid & 15) * 4;
            int c4 = col0 + nq;
            const float* src = (c4 < SPLIT)
                ? (Bl + (long)(kk + krow) * SPLIT + c4)
                : (Br + (long)(kk + krow) * SPLIT + (c4 - SPLIT));
            *(float4*)&Bs[krow][nq] = *(const float4*)src;
        }
        __syncthreads();
#pragma unroll
        for (int k = 0; k < 16; k++) {
            float a[8], b[4];
            *(float4*)&a[0] = *(const float4*)&As[k][ty * 8];
            *(float4*)&a[4] = *(const float4*)&As[k][ty * 8 + 4];
            *(float4*)&b[0] = *(const float4*)&Bs[k][tx * 4];
#pragma unroll
            for (int i = 0; i < 8; i++)
#pragma unroll
                for (int j = 0; j < 4; j++) acc[i][j] += a[i] * b[j];
        }
        __syncthreads();
    }

    // store with bias; choose C0/C1 per 4-col group (SPLIT % 4 == 0)
    int c4 = col0 + tx * 4;
    const bool left = (c4 < SPLIT);
    const float* bp = left ? (bl + c4) : (br + (c4 - SPLIT));
    float4 bv = *(const float4*)bp;
    float* Cb = left ? (C0 + c4) : (C1 + (c4 - SPLIT));
#pragma unroll
    for (int i = 0; i < 8; i++) {
        int r = row0 + ty * 8 + i;
        if (r >= N_NODES) break;
        float4 o;
        o.x = acc[i][0] + bv.x;
        o.y = acc[i][1] + bv.y;
        o.z = acc[i][2] + bv.z;
        o.w = acc[i][3] + bv.w;
        *(float4*)(Cb + (long)r * SPLIT) = o;
    }
}

// ---------------- fused layer-1 node kernel (pipelined) ----------------
__global__ void k_node1(const float* __restrict__ We1,
                        const float* __restrict__ att1,
                        const float* __restrict__ b1) {
    int node = (blockIdx.x * blockDim.x + threadIdx.x) >> 5;
    if (node >= N_NODES) return;
    int lane = threadIdx.x & 31;
    int cb = lane * 8;

    const float4* Rp = (const float4*)(g_xr1 + (long)node * D1 + cb);
    float4 r0 = Rp[0], r1 = Rp[1];
    const float4* Wp = (const float4*)(We1 + cb);
    float4 w0 = Wp[0], w1 = Wp[1];
    const float4* Tp = (const float4*)(att1 + cb);
    float4 a0 = Tp[0], a1 = Tp[1];

    float M = -3.0e38f, D = 0.f;
    float4 v0 = {0.f, 0.f, 0.f, 0.f}, v1 = {0.f, 0.f, 0.f, 0.f};

    int beg = g_off[node], end = g_off[node + 1];

    float e_n = 0.f;
    float4 l0_n = {0,0,0,0}, l1_n = {0,0,0,0};
    if (beg < end) {
        int s = g_ssrc[beg];
        e_n = g_sea[beg];
        const float4* Lp = (const float4*)(g_xl1 + (long)s * D1 + cb);
        l0_n = Lp[0]; l1_n = Lp[1];
    }

    for (int k = beg; k < end; ) {
        float4 l0 = l0_n, l1 = l1_n;
        float eav = e_n;
        k++;
        if (k < end) {   // prefetch next edge while computing current
            int s = g_ssrc[k];
            e_n = g_sea[k];
            const float4* Lp = (const float4*)(g_xl1 + (long)s * D1 + cb);
            l0_n = Lp[0]; l1_n = Lp[1];
        }

        float p = 0.f;
#define TERM(LV, RV, WV, AV) { float t = (LV) + (RV) + eav * (WV); \
        t = (t > 0.f) ? t : NEG_SLOPE * t; p += (AV) * t; }
        TERM(l0.x, r0.x, w0.x, a0.x); TERM(l0.y, r0.y, w0.y, a0.y);
        TERM(l0.z, r0.z, w0.z, a0.z); TERM(l0.w, r0.w, w0.w, a0.w);
        TERM(l1.x, r1.x, w1.x, a1.x); TERM(l1.y, r1.y, w1.y, a1.y);
        TERM(l1.z, r1.z, w1.z, a1.z); TERM(l1.w, r1.w, w1.w, a1.w);
#undef TERM
        p += __shfl_xor_sync(0xffffffffu, p, 4);
        p += __shfl_xor_sync(0xffffffffu, p, 2);
        p += __shfl_xor_sync(0xffffffffu, p, 1);

        float newM = fmaxf(M, p);
        float scale = __expf(M - newM);
        float wgt = __expf(p - newM);
        D = D * scale + wgt;
        v0.x = v0.x * scale + wgt * l0.x; v0.y = v0.y * scale + wgt * l0.y;
        v0.z = v0.z * scale + wgt * l0.z; v0.w = v0.w * scale + wgt * l0.w;
        v1.x = v1.x * scale + wgt * l1.x; v1.y = v1.y * scale + wgt * l1.y;
        v1.z = v1.z * scale + wgt * l1.z; v1.w = v1.w * scale + wgt * l1.w;
        M = newM;
    }

    float inv = 1.f / (D + 1e-16f);
    const float4* Bp = (const float4*)(b1 + cb);
    float4 bb0 = Bp[0], bb1 = Bp[1];
    float4 o0, o1;
    o0.x = fmaxf(v0.x * inv + bb0.x, 0.f); o0.y = fmaxf(v0.y * inv + bb0.y, 0.f);
    o0.z = fmaxf(v0.z * inv + bb0.z, 0.f); o0.w = fmaxf(v0.w * inv + bb0.w, 0.f);
    o1.x = fmaxf(v1.x * inv + bb1.x, 0.f); o1.y = fmaxf(v1.y * inv + bb1.y, 0.f);
    o1.z = fmaxf(v1.z * inv + bb1.z, 0.f); o1.w = fmaxf(v1.w * inv + bb1.w, 0.f);
    float4* Op = (float4*)(g_h1 + (long)node * D1 + cb);
    Op[0] = o0;
    Op[1] = o1;
}

// ---------------- fused layer-2 node kernel (pipelined) ----------------
__global__ void k_node2(const float* __restrict__ We2,
                        const float* __restrict__ att2,
                        const float* __restrict__ b2,
                        float* __restrict__ out) {
    int node = (blockIdx.x * blockDim.x + threadIdx.x) >> 5;
    if (node >= N_NODES) return;
    int lane = threadIdx.x & 31;

    float r = g_xr2[node * OUTC + lane];
    float w = We2[lane];
    float a = att2[lane];

    float M = -3.0e38f, D = 0.f, v = 0.f;

    int beg = g_off[node], end = g_off[node + 1];

    float e_n = 0.f, l_n = 0.f;
    if (beg < end) {
        int s = g_ssrc[beg];
        e_n = g_sea[beg];
        l_n = g_xl2[s * OUTC + lane];
    }

    for (int k = beg; k < end; ) {
        float l = l_n, eav = e_n;
        k++;
        if (k < end) {
            int s = g_ssrc[k];
            e_n = g_sea[k];
            l_n = g_xl2[s * OUTC + lane];
        }

        float t = l + r + eav * w;
        t = (t > 0.f) ? t : NEG_SLOPE * t;
        float p = a * t;
#pragma unroll
        for (int o = 16; o > 0; o >>= 1) p += __shfl_xor_sync(0xffffffffu, p, o);

        float newM = fmaxf(M, p);
        float scale = __expf(M - newM);
        float wgt = __expf(p - newM);
        D = D * scale + wgt;
        v = v * scale + wgt * l;
        M = newM;
    }

    out[node * OUTC + lane] = v / (D + 1e-16f) + b2[lane];
}

// ---------------- launch ----------------
extern "C" void kernel_launch(void* const* d_in, const int* in_sizes, int n_in,
                              void* d_out, int out_size) {
    const float* x    = (const float*)d_in[0];
    const int*   ei   = (const int*)d_in[1];
    const float* ea   = (const float*)d_in[2];
    const float* Wl1  = (const float*)d_in[3];
    const float* bl1  = (const float*)d_in[4];
    const float* Wr1  = (const float*)d_in[5];
    const float* br1  = (const float*)d_in[6];
    const float* We1  = (const float*)d_in[7];
    const float* att1 = (const float*)d_in[8];
    const float* b1   = (const float*)d_in[9];
    const float* Wl2  = (const float*)d_in[10];
    const float* bl2  = (const float*)d_in[11];
    const float* Wr2  = (const float*)d_in[12];
    const float* br2  = (const float*)d_in[13];
    const float* We2  = (const float*)d_in[14];
    const float* att2 = (const float*)d_in[15];
    const float* b2   = (const float*)d_in[16];
    float* out = (float*)d_out;

    // CSR build (counting sort by dst)
    k_zero_deg<<<(N_NODES + 255) / 256, 256>>>();
    k_count<<<(N_EDGES + 255) / 256, 256>>>(ei);
    k_scan1<<<SCAN_NB, SCAN_B>>>();
    k_scan2<<<1, 256>>>();
    k_scan3<<<(N_NODES + 255) / 256, 256>>>();
    k_scatter<<<(N_EDGES + 255) / 256, 256>>>(ei, ea);

    // layer-1 fused GEMM: [xl1|xr1] = x @ [Wl1|Wr1]
    dim3 g1((2 * D1) / 64, (N_NODES + 127) / 128);
    sgemm_dual<0><<<g1, 256>>>(x, Wl1, Wr1, bl1, br1);

    // fused layer-1 attention + aggregation + relu
    int nwb = (N_NODES * 32 + 255) / 256;
    k_node1<<<nwb, 256>>>(We1, att1, b1);

    // layer-2 fused GEMM: [xl2|xr2] = h1 @ [Wl2|Wr2]
    dim3 g2((2 * OUTC) / 64, (N_NODES + 127) / 128);
    sgemm_dual<1><<<g2, 256>>>(nullptr, Wl2, Wr2, bl2, br2);

    // fused layer-2 attention + aggregation + output
    k_node2<<<nwb, 256>>>(We2, att2, b2, out);
}

// round 6
// speedup vs baseline: 2.6900x; 1.0375x over previous
#include <cuda_runtime.h>
#include <cuda_bf16.h>

#define N_NODES 100000
#define N_EDGES 500000
#define FIN 128
#define D1 256
#define NHEADS 4
#define HID 64
#define OUTC 32
#define NEG_SLOPE 0.2f

#define SCAN_B 512
#define SCAN_NB ((N_NODES + SCAN_B - 1) / SCAN_B)   // 196

typedef unsigned long long ull;

// ---------------- scratch (device globals; no allocation) ----------------
__device__ float g_xl1[N_NODES * D1];
__device__ float g_xr1[N_NODES * D1];
__device__ float g_h1[N_NODES * D1];
__device__ float g_xl2[N_NODES * OUTC];
__device__ float g_xr2[N_NODES * OUTC];
__device__ int   g_deg[N_NODES];
__device__ int   g_off[N_NODES + 1];
__device__ int   g_cursor[N_NODES];
__device__ int   g_bsum[SCAN_NB + 1];
__device__ int   g_ssrc[N_EDGES];
__device__ float g_sea[N_EDGES];

// ---------------- f32x2 packed helpers ----------------
__device__ __forceinline__ void fma2(ull& d, ull a, ull b) {
    asm("fma.rn.f32x2 %0, %1, %2, %0;" : "+l"(d) : "l"(a), "l"(b));
}
__device__ __forceinline__ ull splat2(float x) {
    ull r; asm("mov.b64 %0, {%1, %2};" : "=l"(r) : "f"(x), "f"(x)); return r;
}
__device__ __forceinline__ float2 unpack2(ull p) {
    float2 r; asm("mov.b64 {%0, %1}, %2;" : "=f"(r.x), "=f"(r.y) : "l"(p)); return r;
}

// ---------------- CSR build ----------------
__global__ void k_zero_deg() {
    int i = blockIdx.x * blockDim.x + threadIdx.x;
    if (i < N_NODES) g_deg[i] = 0;
}

__global__ void k_count(const int* __restrict__ ei) {
    int i = blockIdx.x * blockDim.x + threadIdx.x;
    if (i < N_EDGES) atomicAdd(&g_deg[ei[N_EDGES + i]], 1);
}

__global__ void k_scan1() {
    __shared__ int sh[SCAN_B];
    int t = threadIdx.x;
    int i = blockIdx.x * SCAN_B + t;
    int v = (i < N_NODES) ? g_deg[i] : 0;
    sh[t] = v;
    __syncthreads();
    for (int off = 1; off < SCAN_B; off <<= 1) {
        int add = (t >= off) ? sh[t - off] : 0;
        __syncthreads();
        sh[t] += add;
        __syncthreads();
    }
    if (i < N_NODES) g_off[i] = sh[t];
    if (t == SCAN_B - 1) g_bsum[blockIdx.x] = sh[t];
}

__global__ void k_scan2() {
    __shared__ int sh[256];
    int t = threadIdx.x;
    int v = (t < SCAN_NB) ? g_bsum[t] : 0;
    sh[t] = v;
    __syncthreads();
    for (int off = 1; off < 256; off <<= 1) {
        int add = (t >= off) ? sh[t - off] : 0;
        __syncthreads();
        sh[t] += add;
        __syncthreads();
    }
    if (t < SCAN_NB) g_bsum[t] = sh[t] - v;
}

__global__ void k_scan3() {
    int i = blockIdx.x * blockDim.x + threadIdx.x;
    if (i < N_NODES) {
        int excl = g_off[i] - g_deg[i] + g_bsum[i / SCAN_B];
        g_off[i] = excl;
        g_cursor[i] = excl;
    }
    if (i == 0) g_off[N_NODES] = N_EDGES;
}

__global__ void k_scatter(const int* __restrict__ ei, const float* __restrict__ ea) {
    int i = blockIdx.x * blockDim.x + threadIdx.x;
    if (i >= N_EDGES) return;
    int d = ei[N_EDGES + i];
    int pos = atomicAdd(&g_cursor[d], 1);
    g_ssrc[pos] = ei[i];
    g_sea[pos] = ea[i];
}

// -------- dual-output SGEMM with packed f32x2 FMA: [C0|C1] = A@[Bl|Br] + bias --
// MODE 0: A=x (K=128), SPLIT=256, BN=128, microtile 8x8 -> g_xl1,g_xr1
// MODE 1: A=g_h1 (K=256), SPLIT=32, BN=64, microtile 8x4 -> g_xl2,g_xr2
// 256 threads = 16x16 thread grid; ty -> 8 rows, tx -> TN cols.
// Accumulators packed along n (2 cols per 64-bit reg); exact fp32 math.
template<int MODE>
__global__ __launch_bounds__(256) void sgemm_dual(const float* __restrict__ Aext,
                                                  const float* __restrict__ Bl,
                                                  const float* __restrict__ Br,
                                                  const float* __restrict__ bl,
                                                  const float* __restrict__ br) {
    constexpr int K     = (MODE == 0) ? FIN : D1;
    constexpr int SPLIT = (MODE == 0) ? D1  : OUTC;
    constexpr int BN    = (MODE == 0) ? 128 : 64;
    constexpr int TN    = BN / 16;    // 8 or 4 cols per thread
    constexpr int NP    = TN / 2;     // packed col-pairs per thread
    const float* A  = (MODE == 0) ? Aext : g_h1;
    float*       C0 = (MODE == 0) ? g_xl1 : g_xl2;
    float*       C1 = (MODE == 0) ? g_xr1 : g_xr2;

    __shared__ float As[16][132];       // [k][m], BM=128 (+4 pad)
    __shared__ float Bs[16][BN + 4];    // [k][n]

    const int tid = threadIdx.x;
    const int tx = tid & 15;
    const int ty = tid >> 4;
    const int row0 = blockIdx.y * 128;
    const int col0 = blockIdx.x * BN;

    ull acc2[8][NP];
#pragma unroll
    for (int i = 0; i < 8; i++)
#pragma unroll
        for (int j = 0; j < NP; j++) acc2[i][j] = 0ULL;

    for (int kk = 0; kk < K; kk += 16) {
        // A tile: 128 rows x 16 k = 512 float4; 2 per thread
#pragma unroll
        for (int i = 0; i < 2; i++) {
            int f = tid * 2 + i;
            int arow = f >> 2;
            int kq = (f & 3) * 4;
            int r = row0 + arow;
            float4 v = {0.f, 0.f, 0.f, 0.f};
            if (r < N_NODES)
                v = *(const float4*)(A + (long)r * K + kk + kq);
            As[kq + 0][arow] = v.x;
            As[kq + 1][arow] = v.y;
            As[kq + 2][arow] = v.z;
            As[kq + 3][arow] = v.w;
        }
        // B tile: 16 k x BN n
        if (MODE == 0) {
#pragma unroll
            for (int i = 0; i < 2; i++) {
                int f = tid * 2 + i;
                int krow = f >> 5;
                int nq = (f & 31) * 4;
                int c4 = col0 + nq;
                const float* src = (c4 < SPLIT)
                    ? (Bl + (long)(kk + krow) * SPLIT + c4)
                    : (Br + (long)(kk + krow) * SPLIT + (c4 - SPLIT));
                *(float4*)&Bs[krow][nq] = *(const float4*)src;
            }
        } else {
            int krow = tid >> 4;
            int nq = (tid & 15) * 4;
            int c4 = col0 + nq;
            const float* src = (c4 < SPLIT)
                ? (Bl + (long)(kk + krow) * SPLIT + c4)
                : (Br + (long)(kk + krow) * SPLIT + (c4 - SPLIT));
            *(float4*)&Bs[krow][nq] = *(const float4*)src;
        }
        __syncthreads();

#pragma unroll
        for (int k = 0; k < 16; k++) {
            float4 a04 = *(const float4*)&As[k][ty * 8];
            float4 a48 = *(const float4*)&As[k][ty * 8 + 4];
            ull aa[8];
            aa[0] = splat2(a04.x); aa[1] = splat2(a04.y);
            aa[2] = splat2(a04.z); aa[3] = splat2(a04.w);
            aa[4] = splat2(a48.x); aa[5] = splat2(a48.y);
            aa[6] = splat2(a48.z); aa[7] = splat2(a48.w);
            const ull* Bp = (const ull*)&Bs[k][tx * TN];
            ull bb[NP];
#pragma unroll
            for (int j = 0; j < NP; j++) bb[j] = Bp[j];
#pragma unroll
            for (int i = 0; i < 8; i++)
#pragma unroll
                for (int j = 0; j < NP; j++) fma2(acc2[i][j], aa[i], bb[j]);
        }
        __syncthreads();
    }

    // store with bias; TN-col chunk never straddles the SPLIT boundary
    int c4 = col0 + tx * TN;
    const bool left = (c4 < SPLIT);
    const float* bp = left ? (bl + c4) : (br + (c4 - SPLIT));
    float* Cb = left ? (C0 + c4) : (C1 + (c4 - SPLIT));

    float bv[TN];
#pragma unroll
    for (int j = 0; j < TN; j++) bv[j] = bp[j];

#pragma unroll
    for (int i = 0; i < 8; i++) {
        int r = row0 + ty * 8 + i;
        if (r >= N_NODES) break;
        float o[TN];
#pragma unroll
        for (int j = 0; j < NP; j++) {
            float2 p = unpack2(acc2[i][j]);
            o[2 * j]     = p.x + bv[2 * j];
            o[2 * j + 1] = p.y + bv[2 * j + 1];
        }
#pragma unroll
        for (int j = 0; j < TN; j += 4)
            *(float4*)(Cb + (long)r * SPLIT + j) = *(float4*)&o[j];
    }
}

// ---------------- fused layer-1 node kernel (pipelined) ----------------
__global__ void k_node1(const float* __restrict__ We1,
                        const float* __restrict__ att1,
                        const float* __restrict__ b1) {
    int node = (blockIdx.x * blockDim.x + threadIdx.x) >> 5;
    if (node >= N_NODES) return;
    int lane = threadIdx.x & 31;
    int cb = lane * 8;

    const float4* Rp = (const float4*)(g_xr1 + (long)node * D1 + cb);
    float4 r0 = Rp[0], r1 = Rp[1];
    const float4* Wp = (const float4*)(We1 + cb);
    float4 w0 = Wp[0], w1 = Wp[1];
    const float4* Tp = (const float4*)(att1 + cb);
    float4 a0 = Tp[0], a1 = Tp[1];

    float M = -3.0e38f, D = 0.f;
    float4 v0 = {0.f, 0.f, 0.f, 0.f}, v1 = {0.f, 0.f, 0.f, 0.f};

    int beg = g_off[node], end = g_off[node + 1];

    float e_n = 0.f;
    float4 l0_n = {0,0,0,0}, l1_n = {0,0,0,0};
    if (beg < end) {
        int s = g_ssrc[beg];
        e_n = g_sea[beg];
        const float4* Lp = (const float4*)(g_xl1 + (long)s * D1 + cb);
        l0_n = Lp[0]; l1_n = Lp[1];
    }

    for (int k = beg; k < end; ) {
        float4 l0 = l0_n, l1 = l1_n;
        float eav = e_n;
        k++;
        if (k < end) {
            int s = g_ssrc[k];
            e_n = g_sea[k];
            const float4* Lp = (const float4*)(g_xl1 + (long)s * D1 + cb);
            l0_n = Lp[0]; l1_n = Lp[1];
        }

        float p = 0.f;
#define TERM(LV, RV, WV, AV) { float t = (LV) + (RV) + eav * (WV); \
        t = (t > 0.f) ? t : NEG_SLOPE * t; p += (AV) * t; }
        TERM(l0.x, r0.x, w0.x, a0.x); TERM(l0.y, r0.y, w0.y, a0.y);
        TERM(l0.z, r0.z, w0.z, a0.z); TERM(l0.w, r0.w, w0.w, a0.w);
        TERM(l1.x, r1.x, w1.x, a1.x); TERM(l1.y, r1.y, w1.y, a1.y);
        TERM(l1.z, r1.z, w1.z, a1.z); TERM(l1.w, r1.w, w1.w, a1.w);
#undef TERM
        p += __shfl_xor_sync(0xffffffffu, p, 4);
        p += __shfl_xor_sync(0xffffffffu, p, 2);
        p += __shfl_xor_sync(0xffffffffu, p, 1);

        float newM = fmaxf(M, p);
        float scale = __expf(M - newM);
        float wgt = __expf(p - newM);
        D = D * scale + wgt;
        v0.x = v0.x * scale + wgt * l0.x; v0.y = v0.y * scale + wgt * l0.y;
        v0.z = v0.z * scale + wgt * l0.z; v0.w = v0.w * scale + wgt * l0.w;
        v1.x = v1.x * scale + wgt * l1.x; v1.y = v1.y * scale + wgt * l1.y;
        v1.z = v1.z * scale + wgt * l1.z; v1.w = v1.w * scale + wgt * l1.w;
        M = newM;
    }

    float inv = 1.f / (D + 1e-16f);
    const float4* Bp = (const float4*)(b1 + cb);
    float4 bb0 = Bp[0], bb1 = Bp[1];
    float4 o0, o1;
    o0.x = fmaxf(v0.x * inv + bb0.x, 0.f); o0.y = fmaxf(v0.y * inv + bb0.y, 0.f);
    o0.z = fmaxf(v0.z * inv + bb0.z, 0.f); o0.w = fmaxf(v0.w * inv + bb0.w, 0.f);
    o1.x = fmaxf(v1.x * inv + bb1.x, 0.f); o1.y = fmaxf(v1.y * inv + bb1.y, 0.f);
    o1.z = fmaxf(v1.z * inv + bb1.z, 0.f); o1.w = fmaxf(v1.w * inv + bb1.w, 0.f);
    float4* Op = (float4*)(g_h1 + (long)node * D1 + cb);
    Op[0] = o0;
    Op[1] = o1;
}

// ---------------- fused layer-2 node kernel (pipelined) ----------------
__global__ void k_node2(const float* __restrict__ We2,
                        const float* __restrict__ att2,
                        const float* __restrict__ b2,
                        float* __restrict__ out) {
    int node = (blockIdx.x * blockDim.x + threadIdx.x) >> 5;
    if (node >= N_NODES) return;
    int lane = threadIdx.x & 31;

    float r = g_xr2[node * OUTC + lane];
    float w = We2[lane];
    float a = att2[lane];

    float M = -3.0e38f, D = 0.f, v = 0.f;

    int beg = g_off[node], end = g_off[node + 1];

    float e_n = 0.f, l_n = 0.f;
    if (beg < end) {
        int s = g_ssrc[beg];
        e_n = g_sea[beg];
        l_n = g_xl2[s * OUTC + lane];
    }

    for (int k = beg; k < end; ) {
        float l = l_n, eav = e_n;
        k++;
        if (k < end) {
            int s = g_ssrc[k];
            e_n = g_sea[k];
            l_n = g_xl2[s * OUTC + lane];
        }

        float t = l + r + eav * w;
        t = (t > 0.f) ? t : NEG_SLOPE * t;
        float p = a * t;
#pragma unroll
        for (int o = 16; o > 0; o >>= 1) p += __shfl_xor_sync(0xffffffffu, p, o);

        float newM = fmaxf(M, p);
        float scale = __expf(M - newM);
        float wgt = __expf(p - newM);
        D = D * scale + wgt;
        v = v * scale + wgt * l;
        M = newM;
    }

    out[node * OUTC + lane] = v / (D + 1e-16f) + b2[lane];
}

// ---------------- launch ----------------
extern "C" void kernel_launch(void* const* d_in, const int* in_sizes, int n_in,
                              void* d_out, int out_size) {
    const float* x    = (const float*)d_in[0];
    const int*   ei   = (const int*)d_in[1];
    const float* ea   = (const float*)d_in[2];
    const float* Wl1  = (const float*)d_in[3];
    const float* bl1  = (const float*)d_in[4];
    const float* Wr1  = (const float*)d_in[5];
    const float* br1  = (const float*)d_in[6];
    const float* We1  = (const float*)d_in[7];
    const float* att1 = (const float*)d_in[8];
    const float* b1   = (const float*)d_in[9];
    const float* Wl2  = (const float*)d_in[10];
    const float* bl2  = (const float*)d_in[11];
    const float* Wr2  = (const float*)d_in[12];
    const float* br2  = (const float*)d_in[13];
    const float* We2  = (const float*)d_in[14];
    const float* att2 = (const float*)d_in[15];
    const float* b2   = (const float*)d_in[16];
    float* out = (float*)d_out;

    // CSR build (counting sort by dst)
    k_zero_deg<<<(N_NODES + 255) / 256, 256>>>();
    k_count<<<(N_EDGES + 255) / 256, 256>>>(ei);
    k_scan1<<<SCAN_NB, SCAN_B>>>();
    k_scan2<<<1, 256>>>();
    k_scan3<<<(N_NODES + 255) / 256, 256>>>();
    k_scatter<<<(N_EDGES + 255) / 256, 256>>>(ei, ea);

    // layer-1 fused GEMM: [xl1|xr1] = x @ [Wl1|Wr1]  (BN=128)
    dim3 g1((2 * D1) / 128, (N_NODES + 127) / 128);
    sgemm_dual<0><<<g1, 256>>>(x, Wl1, Wr1, bl1, br1);

    // fused layer-1 attention + aggregation + relu
    int nwb = (N_NODES * 32 + 255) / 256;
    k_node1<<<nwb, 256>>>(We1, att1, b1);

    // layer-2 fused GEMM: [xl2|xr2] = h1 @ [Wl2|Wr2]  (BN=64)
    dim3 g2(1, (N_NODES + 127) / 128);
    sgemm_dual<1><<<g2, 256>>>(nullptr, Wl2, Wr2, bl2, br2);

    // fused layer-2 attention + aggregation + output
    k_node2<<<nwb, 256>>>(We2, att2, b2, out);
}